// round 2
// baseline (speedup 1.0000x reference)
#include <cuda_runtime.h>

#define NUM_HEADS 12
#define HD 64
#define BATCH 8
#define HH 32
#define WW 32
#define S 1024          // HH*WW
#define C 768
#define BHN 96          // BATCH*NUM_HEADS

// ---------------- scratch (no allocations allowed) ----------------
__device__ __align__(16) float g_q[(size_t)BHN * S * HD];
__device__ __align__(16) float g_k[(size_t)BHN * S * HD];
__device__ __align__(16) float g_v[(size_t)BHN * S * HD];
__device__ __align__(16) float g_relh[(size_t)BHN * S * HH];
__device__ __align__(16) float g_relw[(size_t)BHN * S * WW];
__device__ __align__(16) float g_att[(size_t)BATCH * S * C];

// ---------------- generic 128x128x8 fp32 GEMM, 8x8 microtile ----------------
// MODE 0: C = A @ B + bias, scatter into g_q/g_k/g_v  (A = x, B = w_qkv)
// MODE 1: C = g_att @ B + bias -> Cout (row-major)     (B = w_proj)
template <int MODE>
__global__ __launch_bounds__(256) void gemm_k(const float* __restrict__ A,
                                              const float* __restrict__ B,
                                              const float* __restrict__ bias,
                                              float* __restrict__ Cout,
                                              int M, int N, int K)
{
    __shared__ __align__(16) float As[8][128];
    __shared__ __align__(16) float Bs[8][128];

    const float* Ap = (MODE == 1) ? (const float*)g_att : A;

    const int tid = threadIdx.x;
    const int tx = tid & 15, ty = tid >> 4;
    const int bm = blockIdx.y * 128, bn = blockIdx.x * 128;

    float acc[8][8];
#pragma unroll
    for (int i = 0; i < 8; i++)
#pragma unroll
        for (int j = 0; j < 8; j++) acc[i][j] = 0.f;

    const int arow = tid >> 1, acol = (tid & 1) * 4;
    const int brow = tid >> 5, bcol = (tid & 31) * 4;

    for (int k0 = 0; k0 < K; k0 += 8) {
        float4 av = *(const float4*)(Ap + (size_t)(bm + arow) * K + k0 + acol);
        float4 bv = *(const float4*)(B + (size_t)(k0 + brow) * N + bn + bcol);
        As[acol + 0][arow] = av.x;
        As[acol + 1][arow] = av.y;
        As[acol + 2][arow] = av.z;
        As[acol + 3][arow] = av.w;
        *(float4*)&Bs[brow][bcol] = bv;
        __syncthreads();
#pragma unroll
        for (int kk = 0; kk < 8; kk++) {
            float a[8], b[8];
            *(float4*)(a)     = *(const float4*)&As[kk][ty * 8];
            *(float4*)(a + 4) = *(const float4*)&As[kk][ty * 8 + 4];
            *(float4*)(b)     = *(const float4*)&Bs[kk][tx * 8];
            *(float4*)(b + 4) = *(const float4*)&Bs[kk][tx * 8 + 4];
#pragma unroll
            for (int i = 0; i < 8; i++)
#pragma unroll
                for (int j = 0; j < 8; j++)
                    acc[i][j] = fmaf(a[i], b[j], acc[i][j]);
        }
        __syncthreads();
    }

#pragma unroll
    for (int i = 0; i < 8; i++) {
        const int m = bm + ty * 8 + i;
        const int b = m >> 10, s = m & 1023;
#pragma unroll
        for (int j = 0; j < 8; j++) {
            const int n = bn + tx * 8 + j;
            const float v = acc[i][j] + bias[n];
            if (MODE == 0) {
                const int t   = n / C;          // 0:q 1:k 2:v
                const int rem = n - t * C;
                const int hh  = rem >> 6;       // head
                const int d   = rem & 63;
                float* dst = (t == 0) ? g_q : (t == 1) ? g_k : g_v;
                dst[((size_t)(b * NUM_HEADS + hh) * S + s) * HD + d] = v;
            } else {
                Cout[(size_t)m * N + n] = v;
            }
        }
    }
}

// ---------------- relative-position bias tables ----------------
// mode 0: g_relh[bh][h][w][kh] = sum_d q[bh][h*32+w][d] * table[h-kh+31][d]
// mode 1: g_relw[bh][h][w][kw] = sum_d q[bh][h*32+w][d] * table[w-kw+31][d]
__global__ __launch_bounds__(128) void rel_kernel(const float* __restrict__ table, int mode)
{
    __shared__ float tab[63][65];
    __shared__ float qs[32][65];
    const int bh = blockIdx.y;   // 0..95
    const int h  = blockIdx.x;   // 0..31
    const int tid = threadIdx.x;

    for (int idx = tid; idx < 63 * 64; idx += 128)
        tab[idx >> 6][idx & 63] = table[idx];
    const float* qbase = g_q + ((size_t)bh * S + h * 32) * HD;
    for (int idx = tid; idx < 32 * 64; idx += 128)
        qs[idx >> 6][idx & 63] = qbase[idx];
    __syncthreads();

    float* out = (mode == 0) ? g_relh : g_relw;
    float* obase = out + ((size_t)bh * 32 + h) * 32 * 32;

    for (int o = tid; o < 1024; o += 128) {
        const int w = o >> 5, j = o & 31;
        const int row = (mode == 0) ? (h - j + 31) : (w - j + 31);
        const float* qr = qs[w];
        const float* tr = tab[row];
        float a0 = 0.f, a1 = 0.f, a2 = 0.f, a3 = 0.f;
#pragma unroll
        for (int d = 0; d < 64; d += 4) {
            a0 = fmaf(qr[d + 0], tr[d + 0], a0);
            a1 = fmaf(qr[d + 1], tr[d + 1], a1);
            a2 = fmaf(qr[d + 2], tr[d + 2], a2);
            a3 = fmaf(qr[d + 3], tr[d + 3], a3);
        }
        obase[o] = (a0 + a1) + (a2 + a3);
    }
}

// ---------------- fused attention: one thread = one query row ----------------
// grid (S/128, BHN), 128 threads. Online softmax, 32-key tiles.
// K and V phase-share one smem buffer (fits 48KB static smem with bias tiles).
__global__ __launch_bounds__(128, 2) void attn_kernel()
{
    __shared__ __align__(16) float kvs[32][64];
    __shared__ float rhs[128][33];
    __shared__ float rws[128][33];

    const int bh  = blockIdx.y;
    const int s0  = blockIdx.x * 128;
    const int tid = threadIdx.x;
    const float scale = 0.125f;   // 64^-0.5

    {   // stage this block's bias rows (contiguous in global)
        const float* rh = g_relh + ((size_t)bh * S + s0) * 32;
        const float* rw = g_relw + ((size_t)bh * S + s0) * 32;
        for (int idx = tid; idx < 128 * 32; idx += 128) {
            rhs[idx >> 5][idx & 31] = rh[idx];
            rws[idx >> 5][idx & 31] = rw[idx];
        }
    }

    float qr[64];
    {   // own query row, pre-scaled (bias tables use UNscaled q — already handled)
        const float4* qp = (const float4*)(g_q + ((size_t)bh * S + s0 + tid) * HD);
#pragma unroll
        for (int i = 0; i < 16; i++) {
            float4 t = qp[i];
            qr[4 * i + 0] = t.x * scale;
            qr[4 * i + 1] = t.y * scale;
            qr[4 * i + 2] = t.z * scale;
            qr[4 * i + 3] = t.w * scale;
        }
    }

    float o[64];
#pragma unroll
    for (int d = 0; d < 64; d++) o[d] = 0.f;
    float mrun = -1e30f, lrun = 0.f;

    for (int kt0 = 0; kt0 < S; kt0 += 32) {
        __syncthreads();   // kvs free (prev pv done; also orders bias writes on iter 0)
        {   // load K tile
            const float4* kp = (const float4*)(g_k + ((size_t)bh * S + kt0) * HD);
            float4* d4 = (float4*)kvs;
            for (int i = tid; i < 32 * 16; i += 128) d4[i] = kp[i];
        }
        __syncthreads();

        float sc[32];
        const int kh = kt0 >> 5;            // constant per tile (kt0 % 32 == 0)
        const float rhb = rhs[tid][kh];
#pragma unroll
        for (int t = 0; t < 32; t++) {
            const float4* kk = (const float4*)kvs[t];
            float a0 = 0.f, a1 = 0.f, a2 = 0.f, a3 = 0.f;
#pragma unroll
            for (int i = 0; i < 16; i++) {
                float4 kv = kk[i];
                a0 = fmaf(qr[4 * i + 0], kv.x, a0);
                a1 = fmaf(qr[4 * i + 1], kv.y, a1);
                a2 = fmaf(qr[4 * i + 2], kv.z, a2);
                a3 = fmaf(qr[4 * i + 3], kv.w, a3);
            }
            sc[t] = (a0 + a1) + (a2 + a3) + rhb + rws[tid][t];
        }

        // online softmax (fully thread-local)
        float mt = sc[0];
#pragma unroll
        for (int t = 1; t < 32; t++) mt = fmaxf(mt, sc[t]);
        const float mnew = fmaxf(mrun, mt);
        const float corr = __expf(mrun - mnew);
        lrun *= corr;
#pragma unroll
        for (int d = 0; d < 64; d++) o[d] *= corr;
#pragma unroll
        for (int t = 0; t < 32; t++) {
            sc[t] = __expf(sc[t] - mnew);
            lrun += sc[t];
        }
        mrun = mnew;

        __syncthreads();   // scores extracted, kvs free
        {   // load V tile (same buffer)
            const float4* vp = (const float4*)(g_v + ((size_t)bh * S + kt0) * HD);
            float4* d4 = (float4*)kvs;
            for (int i = tid; i < 32 * 16; i += 128) d4[i] = vp[i];
        }
        __syncthreads();

#pragma unroll
        for (int t = 0; t < 32; t++) {
            const float p = sc[t];
            const float4* vv = (const float4*)kvs[t];
#pragma unroll
            for (int i = 0; i < 16; i++) {
                float4 v4 = vv[i];
                o[4 * i + 0] = fmaf(p, v4.x, o[4 * i + 0]);
                o[4 * i + 1] = fmaf(p, v4.y, o[4 * i + 1]);
                o[4 * i + 2] = fmaf(p, v4.z, o[4 * i + 2]);
                o[4 * i + 3] = fmaf(p, v4.w, o[4 * i + 3]);
            }
        }
    }

    // write (B, s, head*64+d) layout for the proj GEMM
    const float inv = 1.f / lrun;
    const int b = bh / NUM_HEADS, head = bh % NUM_HEADS;
    float4* op = (float4*)(g_att + ((size_t)(b * S + s0 + tid)) * C + head * HD);
#pragma unroll
    for (int i = 0; i < 16; i++) {
        float4 t;
        t.x = o[4 * i + 0] * inv;
        t.y = o[4 * i + 1] * inv;
        t.z = o[4 * i + 2] * inv;
        t.w = o[4 * i + 3] * inv;
        op[i] = t;
    }
}

// ---------------- launch ----------------
extern "C" void kernel_launch(void* const* d_in, const int* in_sizes, int n_in,
                              void* d_out, int out_size)
{
    const float* x     = (const float*)d_in[0];
    const float* wqkv  = (const float*)d_in[1];
    const float* bqkv  = (const float*)d_in[2];
    const float* rph   = (const float*)d_in[3];
    const float* rpw   = (const float*)d_in[4];
    const float* wproj = (const float*)d_in[5];
    const float* bproj = (const float*)d_in[6];
    float* out = (float*)d_out;

    // 1) QKV GEMM -> g_q/g_k/g_v  (M=8192, N=2304, K=768)
    dim3 g1(2304 / 128, 8192 / 128);
    gemm_k<0><<<g1, 256>>>(x, wqkv, bqkv, nullptr, BATCH * S, 3 * C, C);

    // 2) relative-position bias tables
    rel_kernel<<<dim3(32, BHN), 128>>>(rph, 0);
    rel_kernel<<<dim3(32, BHN), 128>>>(rpw, 1);

    // 3) fused attention -> g_att
    attn_kernel<<<dim3(S / 128, BHN), 128>>>();

    // 4) output projection -> d_out  (M=8192, N=768, K=768)
    dim3 g2(768 / 128, 8192 / 128);
    gemm_k<1><<<g2, 256>>>(nullptr, wproj, bproj, out, BATCH * S, C, C);
}

// round 3
// speedup vs baseline: 1.2562x; 1.2562x over previous
#include <cuda_runtime.h>

#define NUM_HEADS 12
#define HD 64
#define BATCH 8
#define HH 32
#define WW 32
#define S 1024          // HH*WW
#define C 768
#define BHN 96          // BATCH*NUM_HEADS

// ---------------- scratch (no allocations allowed) ----------------
__device__ __align__(16) float g_q[(size_t)BHN * S * HD];
__device__ __align__(16) float g_k[(size_t)BHN * S * HD];
__device__ __align__(16) float g_v[(size_t)BHN * S * HD];
__device__ __align__(16) float g_relh[(size_t)BHN * S * HH];
__device__ __align__(16) float g_relw[(size_t)BHN * S * WW];
__device__ __align__(16) float g_att[(size_t)BATCH * S * C];

// ---------------- generic 128x128x8 fp32 GEMM, 8x8 microtile ----------------
template <int MODE>
__global__ __launch_bounds__(256) void gemm_k(const float* __restrict__ A,
                                              const float* __restrict__ B,
                                              const float* __restrict__ bias,
                                              float* __restrict__ Cout,
                                              int M, int N, int K)
{
    __shared__ __align__(16) float As[8][128];
    __shared__ __align__(16) float Bs[8][128];

    const float* Ap = (MODE == 1) ? (const float*)g_att : A;

    const int tid = threadIdx.x;
    const int tx = tid & 15, ty = tid >> 4;
    const int bm = blockIdx.y * 128, bn = blockIdx.x * 128;

    float acc[8][8];
#pragma unroll
    for (int i = 0; i < 8; i++)
#pragma unroll
        for (int j = 0; j < 8; j++) acc[i][j] = 0.f;

    const int arow = tid >> 1, acol = (tid & 1) * 4;
    const int brow = tid >> 5, bcol = (tid & 31) * 4;

    for (int k0 = 0; k0 < K; k0 += 8) {
        float4 av = *(const float4*)(Ap + (size_t)(bm + arow) * K + k0 + acol);
        float4 bv = *(const float4*)(B + (size_t)(k0 + brow) * N + bn + bcol);
        As[acol + 0][arow] = av.x;
        As[acol + 1][arow] = av.y;
        As[acol + 2][arow] = av.z;
        As[acol + 3][arow] = av.w;
        *(float4*)&Bs[brow][bcol] = bv;
        __syncthreads();
#pragma unroll
        for (int kk = 0; kk < 8; kk++) {
            float a[8], b[8];
            *(float4*)(a)     = *(const float4*)&As[kk][ty * 8];
            *(float4*)(a + 4) = *(const float4*)&As[kk][ty * 8 + 4];
            *(float4*)(b)     = *(const float4*)&Bs[kk][tx * 8];
            *(float4*)(b + 4) = *(const float4*)&Bs[kk][tx * 8 + 4];
#pragma unroll
            for (int i = 0; i < 8; i++)
#pragma unroll
                for (int j = 0; j < 8; j++)
                    acc[i][j] = fmaf(a[i], b[j], acc[i][j]);
        }
        __syncthreads();
    }

#pragma unroll
    for (int i = 0; i < 8; i++) {
        const int m = bm + ty * 8 + i;
        const int b = m >> 10, s = m & 1023;
#pragma unroll
        for (int j = 0; j < 8; j++) {
            const int n = bn + tx * 8 + j;
            const float v = acc[i][j] + bias[n];
            if (MODE == 0) {
                const int t   = n / C;          // 0:q 1:k 2:v
                const int rem = n - t * C;
                const int hh  = rem >> 6;       // head
                const int d   = rem & 63;
                float* dst = (t == 0) ? g_q : (t == 1) ? g_k : g_v;
                dst[((size_t)(b * NUM_HEADS + hh) * S + s) * HD + d] = v;
            } else {
                Cout[(size_t)m * N + n] = v;
            }
        }
    }
}

// ---------------- relative-position bias tables ----------------
__global__ __launch_bounds__(128) void rel_kernel(const float* __restrict__ table, int mode)
{
    __shared__ float tab[63][65];
    __shared__ float qs[32][65];
    const int bh = blockIdx.y;
    const int h  = blockIdx.x;
    const int tid = threadIdx.x;

    for (int idx = tid; idx < 63 * 64; idx += 128)
        tab[idx >> 6][idx & 63] = table[idx];
    const float* qbase = g_q + ((size_t)bh * S + h * 32) * HD;
    for (int idx = tid; idx < 32 * 64; idx += 128)
        qs[idx >> 6][idx & 63] = qbase[idx];
    __syncthreads();

    float* out = (mode == 0) ? g_relh : g_relw;
    float* obase = out + ((size_t)bh * 32 + h) * 32 * 32;

    for (int o = tid; o < 1024; o += 128) {
        const int w = o >> 5, j = o & 31;
        const int row = (mode == 0) ? (h - j + 31) : (w - j + 31);
        const float* qr = qs[w];
        const float* tr = tab[row];
        float a0 = 0.f, a1 = 0.f, a2 = 0.f, a3 = 0.f;
#pragma unroll
        for (int d = 0; d < 64; d += 4) {
            a0 = fmaf(qr[d + 0], tr[d + 0], a0);
            a1 = fmaf(qr[d + 1], tr[d + 1], a1);
            a2 = fmaf(qr[d + 2], tr[d + 2], a2);
            a3 = fmaf(qr[d + 3], tr[d + 3], a3);
        }
        obase[o] = (a0 + a1) + (a2 + a3);
    }
}

// ---------------- fused attention, GEMM-style register tiling ----------------
// Block: 128 query rows, 128 threads, 32-key tiles.
// QK: thread = 8q x 4k micro-tile.  PV: thread = 8q x 8d micro-tile.
// Softmax: thread <-> query row via scores tile in smem.
struct AttSmem {
    float q [128][65];   // query rows, pre-scaled
    float sc[128][33];   // scores / probabilities
    float kv[32][65];    // K tile (QK phase) then V tile (PV phase)
    float rws[128][33];  // rel_w bias rows for this block
    float corr[128];     // online-softmax rescale per query
    float invl[128];     // 1/l final per query
};

__global__ __launch_bounds__(128) void attn_kernel()
{
    extern __shared__ char smem_raw[];
    AttSmem& sm = *reinterpret_cast<AttSmem*>(smem_raw);

    const int bh  = blockIdx.y;
    const int s0  = blockIdx.x * 128;
    const int tid = threadIdx.x;
    const int qty = tid >> 3;    // 0..15 -> 8 query rows each
    const int qtx = tid & 7;     // 0..7
    const float scale = 0.125f;  // 64^-0.5

    // stage q (scaled) : 128x64 floats
    {
        const float4* qp = (const float4*)(g_q + ((size_t)bh * S + s0) * HD);
#pragma unroll
        for (int u = 0; u < 16; u++) {
            const int idx4 = tid + 128 * u;
            float4 t = qp[idx4];
            const int r = idx4 >> 4, c = (idx4 & 15) * 4;
            sm.q[r][c + 0] = t.x * scale;
            sm.q[r][c + 1] = t.y * scale;
            sm.q[r][c + 2] = t.z * scale;
            sm.q[r][c + 3] = t.w * scale;
        }
    }
    // stage rel_w bias rows: 128x32
    {
        const float* rp = g_relw + ((size_t)bh * S + s0) * 32;
        for (int idx = tid; idx < 128 * 32; idx += 128)
            sm.rws[idx >> 5][idx & 31] = rp[idx];
    }

    float o[8][8];
#pragma unroll
    for (int i = 0; i < 8; i++)
#pragma unroll
        for (int j = 0; j < 8; j++) o[i][j] = 0.f;

    float mrun = -1e30f, lrun = 0.f;

    for (int kt0 = 0; kt0 < S; kt0 += 32) {
        __syncthreads();            // kv free (prev PV done; iter0: staging done)

        // ---- load K tile ----
        {
            const float4* kp = (const float4*)(g_k + ((size_t)bh * S + kt0) * HD);
            float4 kreg[4];
#pragma unroll
            for (int u = 0; u < 4; u++) kreg[u] = kp[tid + 128 * u];
#pragma unroll
            for (int u = 0; u < 4; u++) {
                const int idx4 = tid + 128 * u;
                const int r = idx4 >> 4, c = (idx4 & 15) * 4;
                sm.kv[r][c + 0] = kreg[u].x;
                sm.kv[r][c + 1] = kreg[u].y;
                sm.kv[r][c + 2] = kreg[u].z;
                sm.kv[r][c + 3] = kreg[u].w;
            }
        }
        __syncthreads();

        // ---- QK micro-tile: 8q x 4k ----
        {
            float acc[8][4];
#pragma unroll
            for (int i = 0; i < 8; i++)
#pragma unroll
                for (int j = 0; j < 4; j++) acc[i][j] = 0.f;

#pragma unroll 8
            for (int kk = 0; kk < 64; kk++) {
                float a[8], b[4];
#pragma unroll
                for (int i = 0; i < 8; i++) a[i] = sm.q[qty * 8 + i][kk];
#pragma unroll
                for (int j = 0; j < 4; j++) b[j] = sm.kv[qtx * 4 + j][kk];
#pragma unroll
                for (int i = 0; i < 8; i++)
#pragma unroll
                    for (int j = 0; j < 4; j++)
                        acc[i][j] = fmaf(a[i], b[j], acc[i][j]);
            }
#pragma unroll
            for (int i = 0; i < 8; i++)
#pragma unroll
                for (int j = 0; j < 4; j++)
                    sm.sc[qty * 8 + i][qtx * 4 + j] = acc[i][j];
        }
        __syncthreads();

        // ---- softmax (thread <-> query row) + V prefetch/stage ----
        {
            // prefetch V early to hide latency under softmax math
            const float4* vp = (const float4*)(g_v + ((size_t)bh * S + kt0) * HD);
            float4 vreg[4];
#pragma unroll
            for (int u = 0; u < 4; u++) vreg[u] = vp[tid + 128 * u];

            const float rhb = g_relh[((size_t)bh * S + s0 + tid) * 32 + (kt0 >> 5)];
            float s[32];
            float mt = -1e30f;
#pragma unroll
            for (int j = 0; j < 32; j++) {
                s[j] = sm.sc[tid][j] + sm.rws[tid][j] + rhb;
                mt = fmaxf(mt, s[j]);
            }
            const float mnew = fmaxf(mrun, mt);
            const float cf = __expf(mrun - mnew);
            lrun *= cf;
#pragma unroll
            for (int j = 0; j < 32; j++) {
                const float p = __expf(s[j] - mnew);
                lrun += p;
                sm.sc[tid][j] = p;
            }
            mrun = mnew;
            sm.corr[tid] = cf;
            if (kt0 == S - 32) sm.invl[tid] = 1.f / lrun;

            // stage V into kv (K reads finished before the last sync)
#pragma unroll
            for (int u = 0; u < 4; u++) {
                const int idx4 = tid + 128 * u;
                const int r = idx4 >> 4, c = (idx4 & 15) * 4;
                sm.kv[r][c + 0] = vreg[u].x;
                sm.kv[r][c + 1] = vreg[u].y;
                sm.kv[r][c + 2] = vreg[u].z;
                sm.kv[r][c + 3] = vreg[u].w;
            }
        }
        __syncthreads();

        // ---- PV micro-tile: 8q x 8d (dims qtx*4..+3 and 32+qtx*4..+3) ----
        {
            float c8[8];
#pragma unroll
            for (int i = 0; i < 8; i++) c8[i] = sm.corr[qty * 8 + i];
#pragma unroll
            for (int i = 0; i < 8; i++)
#pragma unroll
                for (int j = 0; j < 8; j++) o[i][j] *= c8[i];

#pragma unroll 4
            for (int key = 0; key < 32; key++) {
                float vv[8];
#pragma unroll
                for (int j = 0; j < 4; j++) vv[j]     = sm.kv[key][qtx * 4 + j];
#pragma unroll
                for (int j = 0; j < 4; j++) vv[4 + j] = sm.kv[key][32 + qtx * 4 + j];
#pragma unroll
                for (int i = 0; i < 8; i++) {
                    const float p = sm.sc[qty * 8 + i][key];
#pragma unroll
                    for (int j = 0; j < 8; j++)
                        o[i][j] = fmaf(p, vv[j], o[i][j]);
                }
            }
        }
    }

    // ---- epilogue: normalize + write (B, s, head*64+d) ----
    {
        float inv8[8];
#pragma unroll
        for (int i = 0; i < 8; i++) inv8[i] = sm.invl[qty * 8 + i];
        const int b = bh / NUM_HEADS, head = bh % NUM_HEADS;
#pragma unroll
        for (int i = 0; i < 8; i++) {
            const int qrow = s0 + qty * 8 + i;
            float* dst = g_att + ((size_t)(b * S + qrow)) * C + head * HD;
            float4 t0, t1;
            t0.x = o[i][0] * inv8[i];
            t0.y = o[i][1] * inv8[i];
            t0.z = o[i][2] * inv8[i];
            t0.w = o[i][3] * inv8[i];
            t1.x = o[i][4] * inv8[i];
            t1.y = o[i][5] * inv8[i];
            t1.z = o[i][6] * inv8[i];
            t1.w = o[i][7] * inv8[i];
            *(float4*)(dst + qtx * 4)      = t0;
            *(float4*)(dst + 32 + qtx * 4) = t1;
        }
    }
}

// ---------------- launch ----------------
extern "C" void kernel_launch(void* const* d_in, const int* in_sizes, int n_in,
                              void* d_out, int out_size)
{
    const float* x     = (const float*)d_in[0];
    const float* wqkv  = (const float*)d_in[1];
    const float* bqkv  = (const float*)d_in[2];
    const float* rph   = (const float*)d_in[3];
    const float* rpw   = (const float*)d_in[4];
    const float* wproj = (const float*)d_in[5];
    const float* bproj = (const float*)d_in[6];
    float* out = (float*)d_out;

    // 1) QKV GEMM -> g_q/g_k/g_v  (M=8192, N=2304, K=768)
    dim3 g1(2304 / 128, 8192 / 128);
    gemm_k<0><<<g1, 256>>>(x, wqkv, bqkv, nullptr, BATCH * S, 3 * C, C);

    // 2) relative-position bias tables
    rel_kernel<<<dim3(32, BHN), 128>>>(rph, 0);
    rel_kernel<<<dim3(32, BHN), 128>>>(rpw, 1);

    // 3) fused attention -> g_att
    const size_t attn_smem = sizeof(AttSmem);
    cudaFuncSetAttribute(attn_kernel, cudaFuncAttributeMaxDynamicSharedMemorySize,
                         (int)attn_smem);
    attn_kernel<<<dim3(S / 128, BHN), 128, attn_smem>>>();

    // 4) output projection -> d_out  (M=8192, N=768, K=768)
    dim3 g2(768 / 128, 8192 / 128);
    gemm_k<1><<<g2, 256>>>(nullptr, wproj, bproj, out, BATCH * S, C, C);
}